// round 14
// baseline (speedup 1.0000x reference)
#include <cuda_runtime.h>
#include <stdint.h>

#define ALG   248
#define PAD   33            // smem row stride (32 batches + 1 pad word)
#define TB    32            // batches per CTA
#define NWARP 8
#define KPW   31            // 248 / 8 k-values per warp
#define MAXNNZ 65536

// ---------------- device scratch (no allocations allowed) ----------------
__device__ __align__(16) uint2 g_sorted[MAXNNZ + 8];  // {pi | pj<<16, coeff*alpha}
__device__ int g_hist[ALG];
__device__ int g_cursor[ALG];
__device__ int g_seg[ALG + 1];

// ---------------- sort-by-k pipeline ----------------
__global__ void hist_kernel(const int* __restrict__ idx_k, int nnz) {
    int t = blockIdx.x * blockDim.x + threadIdx.x;
    if (t < nnz) atomicAdd(&g_hist[idx_k[t]], 1);
}

__global__ void scan_kernel() {
    if (threadIdx.x == 0) {
        int s = 0;
        for (int k = 0; k < ALG; ++k) {
            g_seg[k]    = s;
            g_cursor[k] = s;
            s += g_hist[k];
        }
        g_seg[ALG] = s;
    }
}

__global__ void scatter_kernel(const int* __restrict__ idx_i,
                               const int* __restrict__ idx_j,
                               const int* __restrict__ idx_k,
                               const float* __restrict__ coeff,
                               const float* __restrict__ alpha,
                               int nnz) {
    int t = blockIdx.x * blockDim.x + threadIdx.x;
    if (t >= nnz) return;
    int k   = idx_k[t];
    int pos = atomicAdd(&g_cursor[k], 1);
    unsigned pi = (unsigned)(idx_i[t] * PAD);       // pre-scaled smem row offset
    unsigned pj = (unsigned)(idx_j[t] * PAD);
    g_sorted[pos] = make_uint2(pi | (pj << 16), __float_as_uint(coeff[t] * alpha[0]));
}

// ---------------- main bilinear kernel ----------------
extern __shared__ float smem[];

__global__ __launch_bounds__(256, 2)
void bracket_kernel(const float* __restrict__ x, const float* __restrict__ y,
                    float* __restrict__ out, int batch) {
    float* xs = smem;                       // [ALG][PAD]
    float* ys = xs + ALG * PAD;             // [ALG][PAD]
    float* os = ys + ALG * PAD;             // [ALG][PAD]
    __shared__ int segs[ALG + 1];

    const int tid  = threadIdx.x;
    const int warp = tid >> 5;
    const int lane = tid & 31;
    const int b0   = blockIdx.x * TB;

    for (int k = tid; k <= ALG; k += blockDim.x) segs[k] = g_seg[k];

    // Stage x,y tile transposed: coalesced global reads, conflict-free smem writes.
    for (int b = warp; b < TB; b += NWARP) {
        const int gb = b0 + b;
        const bool ok = gb < batch;
        const float* xr = x + (size_t)gb * ALG;
        const float* yr = y + (size_t)gb * ALG;
        for (int d = lane; d < ALG; d += 32) {
            xs[d * PAD + b] = ok ? xr[d] : 0.f;
            ys[d * PAD + b] = ok ? yr[d] : 0.f;
        }
    }
    __syncthreads();

    // Each warp owns 31 k-values exclusively -> register accumulation, no atomics.
    const float* xl = xs + lane;            // lane == batch-within-tile
    const float* yl = ys + lane;
    const int k0 = warp * KPW;

    for (int k = k0; k < k0 + KPW; ++k) {
        int t = segs[k];
        const int e = segs[k + 1];
        float acc0 = 0.f, acc1 = 0.f;

        if ((t & 1) && t < e) {             // align to 16B for uint4 loads
            uint2 q = __ldg(&g_sorted[t]);
            acc0 = fmaf(__uint_as_float(q.y) * xl[q.x & 0xFFFFu], yl[q.x >> 16], acc0);
            ++t;
        }
        for (; t + 2 <= e; t += 2) {        // 2 triples per LDG.128
            uint4 q = __ldg((const uint4*)(g_sorted + t));
            acc0 = fmaf(__uint_as_float(q.y) * xl[q.x & 0xFFFFu], yl[q.x >> 16], acc0);
            acc1 = fmaf(__uint_as_float(q.w) * xl[q.z & 0xFFFFu], yl[q.z >> 16], acc1);
        }
        if (t < e) {
            uint2 q = __ldg(&g_sorted[t]);
            acc0 = fmaf(__uint_as_float(q.y) * xl[q.x & 0xFFFFu], yl[q.x >> 16], acc0);
        }
        os[k * PAD + lane] = acc0 + acc1;
    }
    __syncthreads();

    // Coalesced write-out (alpha already folded into coeff).
    for (int b = warp; b < TB; b += NWARP) {
        const int gb = b0 + b;
        if (gb >= batch) continue;
        float* orow = out + (size_t)gb * ALG;
        for (int d = lane; d < ALG; d += 32) orow[d] = os[d * PAD + b];
    }
}

// ---------------- launch ----------------
extern "C" void kernel_launch(void* const* d_in, const int* in_sizes, int n_in,
                              void* d_out, int out_size) {
    const float* x     = (const float*)d_in[0];
    const float* y     = (const float*)d_in[1];
    const int*   idx_i = (const int*)  d_in[2];
    const int*   idx_j = (const int*)  d_in[3];
    const int*   idx_k = (const int*)  d_in[4];
    const float* coeff = (const float*)d_in[5];
    const float* alpha = (const float*)d_in[6];

    int nnz = in_sizes[5];
    if (nnz > MAXNNZ) nnz = MAXNNZ;
    const int batch = in_sizes[0] / ALG;

    void* hist_ptr = nullptr;
    cudaGetSymbolAddress(&hist_ptr, g_hist);
    cudaMemsetAsync(hist_ptr, 0, ALG * sizeof(int));

    const int nb = (nnz + 255) / 256;
    hist_kernel   <<<nb, 256>>>(idx_k, nnz);
    scan_kernel   <<<1, 32>>>();
    scatter_kernel<<<nb, 256>>>(idx_i, idx_j, idx_k, coeff, alpha, nnz);

    const int smem_bytes = 3 * ALG * PAD * (int)sizeof(float);   // 98208 B
    cudaFuncSetAttribute(bracket_kernel,
                         cudaFuncAttributeMaxDynamicSharedMemorySize, smem_bytes);

    const int grid = (batch + TB - 1) / TB;                      // 256 CTAs
    bracket_kernel<<<grid, 256, smem_bytes>>>(x, y, (float*)d_out, batch);
}

// round 15
// speedup vs baseline: 1.2287x; 1.2287x over previous
#include <cuda_runtime.h>
#include <stdint.h>

#define ALG   248
#define PAD   33            // smem row stride in floats (32 batches + 1 pad)
#define ROWB  (PAD * 4)     // row stride in BYTES (132) -> max offset 247*132 = 32604 < 65536
#define TB    32            // batches per CTA
#define NWARP 8
#define KPW   31            // 248 / 8 k-values per warp
#define MAXNNZ 65536

// ---------------- device scratch (no allocations allowed) ----------------
__device__ __align__(16) uint2 g_sorted[MAXNNZ + 8];  // {pi_bytes | pj_bytes<<16, coeff*alpha}
__device__ int g_hist[ALG];
__device__ int g_cursor[ALG];
__device__ int g_seg[ALG + 1];

// ---------------- sort-by-k pipeline ----------------
__global__ void hist_kernel(const int* __restrict__ idx_k, int nnz) {
    int t = blockIdx.x * blockDim.x + threadIdx.x;
    if (t < nnz) atomicAdd(&g_hist[idx_k[t]], 1);
}

// Parallel exclusive scan over 248 bins (one 256-thread block, Hillis-Steele).
__global__ void scan_kernel() {
    __shared__ int buf[256];
    const int t = threadIdx.x;
    int init = (t < ALG) ? g_hist[t] : 0;
    int v = init;
    buf[t] = v;
    __syncthreads();
#pragma unroll
    for (int off = 1; off < 256; off <<= 1) {
        int add = (t >= off) ? buf[t - off] : 0;
        __syncthreads();
        v += add;
        buf[t] = v;
        __syncthreads();
    }
    if (t < ALG) {
        int ex = v - init;                  // exclusive prefix
        g_seg[t]    = ex;
        g_cursor[t] = ex;
        if (t == ALG - 1) g_seg[ALG] = v;   // total nnz
    }
}

__global__ void scatter_kernel(const int* __restrict__ idx_i,
                               const int* __restrict__ idx_j,
                               const int* __restrict__ idx_k,
                               const float* __restrict__ coeff,
                               const float* __restrict__ alpha,
                               int nnz) {
    int t = blockIdx.x * blockDim.x + threadIdx.x;
    if (t >= nnz) return;
    int k   = idx_k[t];
    int pos = atomicAdd(&g_cursor[k], 1);
    unsigned pi = (unsigned)(idx_i[t] * ROWB);       // BYTE offset into smem tile
    unsigned pj = (unsigned)(idx_j[t] * ROWB);
    g_sorted[pos] = make_uint2(pi | (pj << 16), __float_as_uint(coeff[t] * alpha[0]));
}

// ---------------- main bilinear kernel ----------------
extern __shared__ float smem[];

__device__ __forceinline__ float gpair(const char* xb, const char* yb, unsigned p, float c) {
    float xv = *(const float*)(xb + (p & 0xFFFFu));
    float yv = *(const float*)(yb + (p >> 16));
    return c * xv * yv;   // compiler fuses into FMA chain at call site via fmaf below
}

__global__ __launch_bounds__(256, 3)
void bracket_kernel(const float* __restrict__ x, const float* __restrict__ y,
                    float* __restrict__ out, int batch) {
    float* xs = smem;                       // [ALG][PAD]
    float* ys = xs + ALG * PAD;             // [ALG][PAD]
    __shared__ int segs[ALG + 1];

    const int tid  = threadIdx.x;
    const int warp = tid >> 5;
    const int lane = tid & 31;
    const int b0   = blockIdx.x * TB;

    for (int k = tid; k <= ALG; k += blockDim.x) segs[k] = g_seg[k];

    // Stage x,y tile transposed: coalesced global reads, conflict-free smem writes.
    for (int b = warp; b < TB; b += NWARP) {
        const int gb = b0 + b;
        const bool ok = gb < batch;
        const float* xr = x + (size_t)gb * ALG;
        const float* yr = y + (size_t)gb * ALG;
        for (int d = lane; d < ALG; d += 32) {
            xs[d * PAD + b] = ok ? xr[d] : 0.f;
            ys[d * PAD + b] = ok ? yr[d] : 0.f;
        }
    }
    __syncthreads();

    // Each warp owns KPW k-values exclusively -> register accumulation, no atomics.
    const char* xb = (const char*)xs + lane * 4;
    const char* yb = (const char*)ys + lane * 4;
    const int k0 = warp * KPW;

    float acc[KPW];
#pragma unroll
    for (int kk = 0; kk < KPW; ++kk) {
        int t = segs[k0 + kk];
        const int e = segs[k0 + kk + 1];
        float a0 = 0.f, a1 = 0.f, a2 = 0.f, a3 = 0.f;

        if ((t & 1) && t < e) {             // align to 16B for uint4 loads
            uint2 q = __ldg(&g_sorted[t]);
            a0 += gpair(xb, yb, q.x, __uint_as_float(q.y));
            ++t;
        }
        for (; t + 4 <= e; t += 4) {        // 4 triples: 2x LDG.128, 4 indep chains
            uint4 q0 = __ldg((const uint4*)(g_sorted + t));
            uint4 q1 = __ldg((const uint4*)(g_sorted + t + 2));
            a0 += gpair(xb, yb, q0.x, __uint_as_float(q0.y));
            a1 += gpair(xb, yb, q0.z, __uint_as_float(q0.w));
            a2 += gpair(xb, yb, q1.x, __uint_as_float(q1.y));
            a3 += gpair(xb, yb, q1.z, __uint_as_float(q1.w));
        }
        if (t + 2 <= e) {
            uint4 q = __ldg((const uint4*)(g_sorted + t));
            a0 += gpair(xb, yb, q.x, __uint_as_float(q.y));
            a1 += gpair(xb, yb, q.z, __uint_as_float(q.w));
            t += 2;
        }
        if (t < e) {
            uint2 q = __ldg(&g_sorted[t]);
            a2 += gpair(xb, yb, q.x, __uint_as_float(q.y));
        }
        acc[kk] = (a0 + a1) + (a2 + a3);
    }
    __syncthreads();                        // xs/ys dead -> reuse xs as output stage

    float* os = xs;                         // [ALG][PAD], exactly fits
#pragma unroll
    for (int kk = 0; kk < KPW; ++kk)
        os[(k0 + kk) * PAD + lane] = acc[kk];
    __syncthreads();

    // Coalesced write-out (alpha already folded into coeff).
    for (int b = warp; b < TB; b += NWARP) {
        const int gb = b0 + b;
        if (gb >= batch) continue;
        float* orow = out + (size_t)gb * ALG;
        for (int d = lane; d < ALG; d += 32) orow[d] = os[d * PAD + b];
    }
}

// ---------------- launch ----------------
extern "C" void kernel_launch(void* const* d_in, const int* in_sizes, int n_in,
                              void* d_out, int out_size) {
    const float* x     = (const float*)d_in[0];
    const float* y     = (const float*)d_in[1];
    const int*   idx_i = (const int*)  d_in[2];
    const int*   idx_j = (const int*)  d_in[3];
    const int*   idx_k = (const int*)  d_in[4];
    const float* coeff = (const float*)d_in[5];
    const float* alpha = (const float*)d_in[6];

    int nnz = in_sizes[5];
    if (nnz > MAXNNZ) nnz = MAXNNZ;
    const int batch = in_sizes[0] / ALG;

    void* hist_ptr = nullptr;
    cudaGetSymbolAddress(&hist_ptr, g_hist);
    cudaMemsetAsync(hist_ptr, 0, ALG * sizeof(int));

    const int nb = (nnz + 255) / 256;
    hist_kernel   <<<nb, 256>>>(idx_k, nnz);
    scan_kernel   <<<1, 256>>>();
    scatter_kernel<<<nb, 256>>>(idx_i, idx_j, idx_k, coeff, alpha, nnz);

    const int smem_bytes = 2 * ALG * PAD * (int)sizeof(float);   // 65472 B
    cudaFuncSetAttribute(bracket_kernel,
                         cudaFuncAttributeMaxDynamicSharedMemorySize, smem_bytes);

    const int grid = (batch + TB - 1) / TB;                      // 256 CTAs
    bracket_kernel<<<grid, 256, smem_bytes>>>(x, y, (float*)d_out, batch);
}